// round 3
// baseline (speedup 1.0000x reference)
#include <cuda_runtime.h>
#include <cuda_bf16.h>

// ---------------------------------------------------------------------------
// HeteroRGCN layer, atomic-free formulation:
//   mean_dst(W x_src + b) = W * mean_dst(x_src) + b   (b masked where deg==0)
// Pipeline per relation:
//   1. histogram of dst degrees
//   2. prefix scan -> CSR offsets
//   3. reorder edges by dst (int atomic cursor)
//   4. segment-mean of RAW source features (one warp per dst, register acc)
//   5. tiled Linear on the 100K x 64 means, bias masked by deg>0, -> d_out
// ---------------------------------------------------------------------------

#define MAXN 100000
#define MAXE 1000000
#define SCAN_B 256
#define NBLK ((MAXN + 1 + SCAN_B - 1) / SCAN_B)   // 391 blocks for 100001 elems

// rel 1 (clicks): dst = items.   rel 2 (clicked_by): dst = users.
__device__ int   g_off1[MAXN + 1];
__device__ int   g_off2[MAXN + 1];
__device__ int   g_cur1[MAXN + 1];
__device__ int   g_cur2[MAXN + 1];
__device__ int   g_csr1[MAXE];
__device__ int   g_csr2[MAXE];
__device__ int   g_bsum1[512];
__device__ int   g_bsum2[512];
__device__ float g_tmp_item[MAXN * 64];   // mean feat_user at item dsts
__device__ float g_tmp_user[MAXN * 64];   // mean feat_item at user dsts

// ---------------------------------------------------------------------------
__global__ void zero_cnt(int n1, int n2) {
    int i = blockIdx.x * blockDim.x + threadIdx.x;
    if (i <= n1) g_off1[i] = 0;
    if (i <= n2) g_off2[i] = 0;
}

__global__ void hist_kernel(const int* __restrict__ dst1, int E1,
                            const int* __restrict__ dst2, int E2) {
    int i = blockIdx.x * blockDim.x + threadIdx.x;
    if (i < E1) atomicAdd(&g_off1[__ldg(dst1 + i) + 1], 1);
    if (i < E2) atomicAdd(&g_off2[__ldg(dst2 + i) + 1], 1);
}

// Inclusive scan, 3-phase. Phase 1: per-block scan + block sums.
__global__ void scan_block(int sel, int n) {
    __shared__ int s[SCAN_B];
    int* data = sel ? g_off2 : g_off1;
    int* bsum = sel ? g_bsum2 : g_bsum1;
    int t = threadIdx.x;
    int i = blockIdx.x * SCAN_B + t;
    s[t] = (i < n) ? data[i] : 0;
    __syncthreads();
#pragma unroll
    for (int d = 1; d < SCAN_B; d <<= 1) {
        int x = (t >= d) ? s[t - d] : 0;
        __syncthreads();
        s[t] += x;
        __syncthreads();
    }
    if (i < n) data[i] = s[t];
    if (t == SCAN_B - 1) bsum[blockIdx.x] = s[t];
}

// Phase 2: scan the <=512 block sums in one block.
__global__ void scan_bsums(int sel, int nb) {
    __shared__ int s[512];
    int* bsum = sel ? g_bsum2 : g_bsum1;
    int t = threadIdx.x;
    s[t] = (t < nb) ? bsum[t] : 0;
    __syncthreads();
#pragma unroll
    for (int d = 1; d < 512; d <<= 1) {
        int x = (t >= d) ? s[t - d] : 0;
        __syncthreads();
        s[t] += x;
        __syncthreads();
    }
    if (t < nb) bsum[t] = s[t];
}

// Phase 3: add scanned block sums; also initialize the reorder cursor.
__global__ void scan_add(int sel, int n) {
    int* data = sel ? g_off2 : g_off1;
    int* cur  = sel ? g_cur2 : g_cur1;
    const int* bsum = sel ? g_bsum2 : g_bsum1;
    int i = blockIdx.x * SCAN_B + threadIdx.x;
    if (i < n) {
        int v = data[i] + (blockIdx.x > 0 ? bsum[blockIdx.x - 1] : 0);
        data[i] = v;
        cur[i]  = v;
    }
}

__global__ void reorder_kernel(const int* __restrict__ s1, const int* __restrict__ d1, int E1,
                               const int* __restrict__ s2, const int* __restrict__ d2, int E2) {
    int i = blockIdx.x * blockDim.x + threadIdx.x;
    if (i < E1) {
        int p = atomicAdd(&g_cur1[__ldg(d1 + i)], 1);
        g_csr1[p] = __ldg(s1 + i);
    }
    if (i < E2) {
        int p = atomicAdd(&g_cur2[__ldg(d2 + i)], 1);
        g_csr2[p] = __ldg(s2 + i);
    }
}

// ---------------------------------------------------------------------------
// Segment-mean of raw features. One warp per dst node. Each half-warp (16
// lanes, one float4 per lane = full 64-f32 row) handles alternate edges;
// halves combined with shfl.xor. Register accumulation, zero atomics.
// sel: 0 -> csr1/off1 -> g_tmp_item, 1 -> csr2/off2 -> g_tmp_user
// ---------------------------------------------------------------------------
__global__ void segmean_kernel(int sel, const float4* __restrict__ feat, int N) {
    const int* csr = sel ? g_csr2 : g_csr1;
    const int* off = sel ? g_off2 : g_off1;
    float4* tmp = sel ? (float4*)g_tmp_user : (float4*)g_tmp_item;

    int w = (blockIdx.x * blockDim.x + threadIdx.x) >> 5;
    int lane = threadIdx.x & 31;
    if (w >= N) return;

    int beg = __ldg(off + w), end = __ldg(off + w + 1);
    int half = lane >> 4, q = lane & 15;

    float4 acc = make_float4(0.f, 0.f, 0.f, 0.f);
    for (int e = beg + half; e < end; e += 2) {
        int s = __ldg(csr + e);
        float4 v = __ldg(feat + (long long)s * 16 + q);
        acc.x += v.x; acc.y += v.y; acc.z += v.z; acc.w += v.w;
    }
    // combine the two halves
    acc.x += __shfl_xor_sync(0xffffffffu, acc.x, 16);
    acc.y += __shfl_xor_sync(0xffffffffu, acc.y, 16);
    acc.z += __shfl_xor_sync(0xffffffffu, acc.z, 16);
    acc.w += __shfl_xor_sync(0xffffffffu, acc.w, 16);

    float inv = (end > beg) ? 1.0f / (float)(end - beg) : 0.0f;
    acc.x *= inv; acc.y *= inv; acc.z *= inv; acc.w *= inv;

    if (lane < 16) tmp[(long long)w * 16 + q] = acc;
}

// ---------------------------------------------------------------------------
// out = X @ W^T + (deg>0 ? b : 0), written straight into d_out.
// Block: 256 threads -> 16 rows x 64 cols, W + X tile in smem.
// ---------------------------------------------------------------------------
__global__ void linear_kernel(int sel,
                              const float4* __restrict__ W,
                              const float*  __restrict__ b,
                              float* __restrict__ out, int N) {
    __shared__ float4 Ws[64][17];
    __shared__ float4 Xs[16][17];
    __shared__ float  bs[64];
    __shared__ int    mk[16];

    const float4* X  = sel ? (const float4*)g_tmp_user : (const float4*)g_tmp_item;
    const int*    off = sel ? g_off2 : g_off1;

    int tid = threadIdx.x;
    for (int i = tid; i < 64 * 16; i += 256) Ws[i >> 4][i & 15] = W[i];
    if (tid < 64) bs[tid] = b[tid];

    int row0 = blockIdx.x * 16;
    if (tid < 16) {
        int r = row0 + tid;
        mk[tid] = (r < N && off[r + 1] > off[r]) ? 1 : 0;
    }
    {
        int r = tid >> 4, kk = tid & 15;
        int grow = row0 + r;
        Xs[r][kk] = (grow < N) ? X[(long long)grow * 16 + kk]
                               : make_float4(0.f, 0.f, 0.f, 0.f);
    }
    __syncthreads();

    int c = tid & 63;
    int rsub = tid >> 6;

    float acc0 = mk[4 * rsub + 0] ? bs[c] : 0.f;
    float acc1 = mk[4 * rsub + 1] ? bs[c] : 0.f;
    float acc2 = mk[4 * rsub + 2] ? bs[c] : 0.f;
    float acc3 = mk[4 * rsub + 3] ? bs[c] : 0.f;

#pragma unroll
    for (int k = 0; k < 16; k++) {
        float4 w  = Ws[c][k];
        float4 x0 = Xs[4 * rsub + 0][k];
        float4 x1 = Xs[4 * rsub + 1][k];
        float4 x2 = Xs[4 * rsub + 2][k];
        float4 x3 = Xs[4 * rsub + 3][k];
        acc0 += x0.x * w.x + x0.y * w.y + x0.z * w.z + x0.w * w.w;
        acc1 += x1.x * w.x + x1.y * w.y + x1.z * w.z + x1.w * w.w;
        acc2 += x2.x * w.x + x2.y * w.y + x2.z * w.z + x2.w * w.w;
        acc3 += x3.x * w.x + x3.y * w.y + x3.z * w.z + x3.w * w.w;
    }

    int rr = row0 + 4 * rsub;
    if (rr + 0 < N) out[(long long)(rr + 0) * 64 + c] = acc0;
    if (rr + 1 < N) out[(long long)(rr + 1) * 64 + c] = acc1;
    if (rr + 2 < N) out[(long long)(rr + 2) * 64 + c] = acc2;
    if (rr + 3 < N) out[(long long)(rr + 3) * 64 + c] = acc3;
}

// ---------------------------------------------------------------------------
extern "C" void kernel_launch(void* const* d_in, const int* in_sizes, int n_in,
                              void* d_out, int out_size) {
    const float* feat_user  = (const float*)d_in[0];
    const float* feat_item  = (const float*)d_in[1];
    const int*   src_clicks = (const int*)d_in[2];
    const int*   dst_clicks = (const int*)d_in[3];
    const int*   src_cb     = (const int*)d_in[4];
    const int*   dst_cb     = (const int*)d_in[5];
    const float* W_clicks   = (const float*)d_in[6];
    const float* b_clicks   = (const float*)d_in[7];
    const float* W_cb       = (const float*)d_in[8];
    const float* b_cb       = (const float*)d_in[9];

    int n_user = in_sizes[0] / 64;
    int n_item = in_sizes[1] / 64;
    int E1 = in_sizes[2];   // clicks edges      (user -> item)
    int E2 = in_sizes[4];   // clicked_by edges  (item -> user)
    int Emax = E1 > E2 ? E1 : E2;

    float* out_user = (float*)d_out;                         // [n_user, 64]
    float* out_item = out_user + (long long)n_user * 64;     // [n_item, 64]

    // ---- CSR build (both relations interleaved where possible) ----
    zero_cnt<<<NBLK, SCAN_B>>>(n_item, n_user);
    hist_kernel<<<(Emax + 255) / 256, 256>>>(dst_clicks, E1, dst_cb, E2);

    int n1 = n_item + 1, n2 = n_user + 1;
    int nb1 = (n1 + SCAN_B - 1) / SCAN_B;
    int nb2 = (n2 + SCAN_B - 1) / SCAN_B;
    scan_block<<<nb1, SCAN_B>>>(0, n1);
    scan_block<<<nb2, SCAN_B>>>(1, n2);
    scan_bsums<<<1, 512>>>(0, nb1);
    scan_bsums<<<1, 512>>>(1, nb2);
    scan_add<<<nb1, SCAN_B>>>(0, n1);
    scan_add<<<nb2, SCAN_B>>>(1, n2);

    reorder_kernel<<<(Emax + 255) / 256, 256>>>(src_clicks, dst_clicks, E1,
                                                src_cb, dst_cb, E2);

    // ---- segment-mean of raw features (one warp per dst) ----
    {
        int warps = n_item;
        int blocks = (warps * 32 + 255) / 256;
        segmean_kernel<<<blocks, 256>>>(0, (const float4*)feat_user, n_item);
    }
    {
        int warps = n_user;
        int blocks = (warps * 32 + 255) / 256;
        segmean_kernel<<<blocks, 256>>>(1, (const float4*)feat_item, n_user);
    }

    // ---- Linear on the means, bias masked by deg>0, straight to d_out ----
    linear_kernel<<<(n_item + 15) / 16, 256>>>(0, (const float4*)W_clicks,
                                               b_clicks, out_item, n_item);
    linear_kernel<<<(n_user + 15) / 16, 256>>>(1, (const float4*)W_cb,
                                               b_cb, out_user, n_user);
}

// round 4
// speedup vs baseline: 1.3856x; 1.3856x over previous
#include <cuda_runtime.h>
#include <cuda_bf16.h>

// ---------------------------------------------------------------------------
// HeteroRGCN layer, atomic-free formulation:
//   mean_dst(W x_src + b) = W * mean_dst(x_src) + b   (b masked where deg==0)
// Pipeline (each kernel handles BOTH relations; 8 launches total):
//   1. zero counters       2. histogram dst degrees
//   3-5. prefix scan -> CSR offsets (3-phase)
//   6. reorder edges by dst (atomic cursor)
//   7. segment-mean of raw src features (warp/dst, contiguous-half + unroll)
//   8. Linear on the means, bias masked by deg>0, straight to d_out
// ---------------------------------------------------------------------------

#define MAXN 100000
#define MAXE 1000000
#define SCAN_B 256

// rel 1 (clicks): dst = items.   rel 2 (clicked_by): dst = users.
__device__ int   g_off1[MAXN + 1];
__device__ int   g_off2[MAXN + 1];
__device__ int   g_cur1[MAXN + 1];
__device__ int   g_cur2[MAXN + 1];
__device__ int   g_csr1[MAXE];
__device__ int   g_csr2[MAXE];
__device__ int   g_bsum1[512];
__device__ int   g_bsum2[512];
__device__ float g_tmp_item[MAXN * 64];   // mean feat_user at item dsts
__device__ float g_tmp_user[MAXN * 64];   // mean feat_item at user dsts

// ---------------------------------------------------------------------------
__global__ void zero_cnt(int n1, int n2) {
    int i = blockIdx.x * blockDim.x + threadIdx.x;
    if (i <= n1) g_off1[i] = 0;
    if (i <= n2) g_off2[i] = 0;
}

__global__ void hist_kernel(const int* __restrict__ dst1, int E1,
                            const int* __restrict__ dst2, int E2) {
    int i = blockIdx.x * blockDim.x + threadIdx.x;
    if (i < E1) atomicAdd(&g_off1[__ldg(dst1 + i) + 1], 1);
    if (i < E2) atomicAdd(&g_off2[__ldg(dst2 + i) + 1], 1);
}

// Inclusive scan, 3-phase, both relations in one grid.
// blocks [0, nb1) -> rel1, [nb1, nb1+nb2) -> rel2.
__global__ void scan_block(int nb1, int n1, int n2) {
    __shared__ int s[SCAN_B];
    int sel = (blockIdx.x >= nb1) ? 1 : 0;
    int blk = sel ? blockIdx.x - nb1 : blockIdx.x;
    int n   = sel ? n2 : n1;
    int* data = sel ? g_off2 : g_off1;
    int* bsum = sel ? g_bsum2 : g_bsum1;

    int t = threadIdx.x;
    int i = blk * SCAN_B + t;
    s[t] = (i < n) ? data[i] : 0;
    __syncthreads();
#pragma unroll
    for (int d = 1; d < SCAN_B; d <<= 1) {
        int x = (t >= d) ? s[t - d] : 0;
        __syncthreads();
        s[t] += x;
        __syncthreads();
    }
    if (i < n) data[i] = s[t];
    if (t == SCAN_B - 1) bsum[blk] = s[t];
}

// Phase 2: two blocks, one per relation, scan the <=512 block sums.
__global__ void scan_bsums(int nb1, int nb2) {
    __shared__ int s[512];
    int sel = blockIdx.x;
    int nb  = sel ? nb2 : nb1;
    int* bsum = sel ? g_bsum2 : g_bsum1;
    int t = threadIdx.x;
    s[t] = (t < nb) ? bsum[t] : 0;
    __syncthreads();
#pragma unroll
    for (int d = 1; d < 512; d <<= 1) {
        int x = (t >= d) ? s[t - d] : 0;
        __syncthreads();
        s[t] += x;
        __syncthreads();
    }
    if (t < nb) bsum[t] = s[t];
}

// Phase 3: add scanned block sums; also initialize the reorder cursor.
__global__ void scan_add(int nb1, int n1, int n2) {
    int sel = (blockIdx.x >= nb1) ? 1 : 0;
    int blk = sel ? blockIdx.x - nb1 : blockIdx.x;
    int n   = sel ? n2 : n1;
    int* data = sel ? g_off2 : g_off1;
    int* cur  = sel ? g_cur2 : g_cur1;
    const int* bsum = sel ? g_bsum2 : g_bsum1;
    int i = blk * SCAN_B + threadIdx.x;
    if (i < n) {
        int v = data[i] + (blk > 0 ? bsum[blk - 1] : 0);
        data[i] = v;
        cur[i]  = v;
    }
}

__global__ void reorder_kernel(const int* __restrict__ s1, const int* __restrict__ d1, int E1,
                               const int* __restrict__ s2, const int* __restrict__ d2, int E2) {
    int i = blockIdx.x * blockDim.x + threadIdx.x;
    if (i < E1) {
        int p = atomicAdd(&g_cur1[__ldg(d1 + i)], 1);
        g_csr1[p] = __ldg(s1 + i);
    }
    if (i < E2) {
        int p = atomicAdd(&g_cur2[__ldg(d2 + i)], 1);
        g_csr2[p] = __ldg(s2 + i);
    }
}

// ---------------------------------------------------------------------------
// Segment-mean of raw features, both relations in one grid.
// One warp per dst node. Each HALF-warp (16 lanes = one full 64-f32 row via
// float4/lane) takes a CONTIGUOUS half of the segment and unrolls x2 with
// independent accumulators -> >=4 feature loads in flight per warp.
// ---------------------------------------------------------------------------
__global__ void segmean_kernel(const float4* __restrict__ feat1,
                               const float4* __restrict__ feat2,
                               int n_item, int n_user) {
    int gw = (blockIdx.x * blockDim.x + threadIdx.x) >> 5;
    int lane = threadIdx.x & 31;
    if (gw >= n_item + n_user) return;

    int sel = (gw >= n_item) ? 1 : 0;
    int w   = sel ? gw - n_item : gw;
    const int*    csr  = sel ? g_csr2 : g_csr1;
    const int*    off  = sel ? g_off2 : g_off1;
    const float4* feat = sel ? feat2 : feat1;
    float4*       tmp  = sel ? (float4*)g_tmp_user : (float4*)g_tmp_item;

    int beg = __ldg(off + w), end = __ldg(off + w + 1);
    int cnt = end - beg;
    int half = lane >> 4, q = lane & 15;

    // contiguous split: half 0 gets ceil(cnt/2), half 1 the rest
    int c0  = (cnt + 1) >> 1;
    int myb = beg + (half ? c0 : 0);
    int myc = half ? (cnt - c0) : c0;

    float4 a0 = make_float4(0.f, 0.f, 0.f, 0.f);
    float4 a1 = make_float4(0.f, 0.f, 0.f, 0.f);

    int i = 0;
    for (; i + 2 <= myc; i += 2) {
        int s0 = __ldg(csr + myb + i);
        int s1 = __ldg(csr + myb + i + 1);
        float4 v0 = __ldg(feat + (long long)s0 * 16 + q);
        float4 v1 = __ldg(feat + (long long)s1 * 16 + q);
        a0.x += v0.x; a0.y += v0.y; a0.z += v0.z; a0.w += v0.w;
        a1.x += v1.x; a1.y += v1.y; a1.z += v1.z; a1.w += v1.w;
    }
    if (i < myc) {
        int s0 = __ldg(csr + myb + i);
        float4 v0 = __ldg(feat + (long long)s0 * 16 + q);
        a0.x += v0.x; a0.y += v0.y; a0.z += v0.z; a0.w += v0.w;
    }

    a0.x += a1.x; a0.y += a1.y; a0.z += a1.z; a0.w += a1.w;

    // combine the two half-warps
    a0.x += __shfl_xor_sync(0xffffffffu, a0.x, 16);
    a0.y += __shfl_xor_sync(0xffffffffu, a0.y, 16);
    a0.z += __shfl_xor_sync(0xffffffffu, a0.z, 16);
    a0.w += __shfl_xor_sync(0xffffffffu, a0.w, 16);

    float inv = (cnt > 0) ? 1.0f / (float)cnt : 0.0f;
    a0.x *= inv; a0.y *= inv; a0.z *= inv; a0.w *= inv;

    if (lane < 16) tmp[(long long)w * 16 + q] = a0;
}

// ---------------------------------------------------------------------------
// out = X @ W^T + (deg>0 ? b : 0), both relations via blockIdx.y.
// Block: 256 threads -> 16 rows x 64 cols, W + X tile in smem.
// ---------------------------------------------------------------------------
__global__ void linear_kernel(const float4* __restrict__ W1, const float* __restrict__ b1,
                              const float4* __restrict__ W2, const float* __restrict__ b2,
                              float* __restrict__ out_item, float* __restrict__ out_user,
                              int n_item, int n_user) {
    __shared__ float4 Ws[64][17];
    __shared__ float4 Xs[16][17];
    __shared__ float  bs[64];
    __shared__ int    mk[16];

    int sel = blockIdx.y;
    const float4* W   = sel ? W2 : W1;
    const float*  b   = sel ? b2 : b1;
    const float4* X   = sel ? (const float4*)g_tmp_user : (const float4*)g_tmp_item;
    const int*    off = sel ? g_off2 : g_off1;
    float*        out = sel ? out_user : out_item;
    int           N   = sel ? n_user : n_item;

    int row0 = blockIdx.x * 16;
    if (row0 >= N) return;

    int tid = threadIdx.x;
    for (int i = tid; i < 64 * 16; i += 256) Ws[i >> 4][i & 15] = W[i];
    if (tid < 64) bs[tid] = b[tid];
    if (tid < 16) {
        int r = row0 + tid;
        mk[tid] = (r < N && off[r + 1] > off[r]) ? 1 : 0;
    }
    {
        int r = tid >> 4, kk = tid & 15;
        int grow = row0 + r;
        Xs[r][kk] = (grow < N) ? X[(long long)grow * 16 + kk]
                               : make_float4(0.f, 0.f, 0.f, 0.f);
    }
    __syncthreads();

    int c = tid & 63;
    int rsub = tid >> 6;

    float acc0 = mk[4 * rsub + 0] ? bs[c] : 0.f;
    float acc1 = mk[4 * rsub + 1] ? bs[c] : 0.f;
    float acc2 = mk[4 * rsub + 2] ? bs[c] : 0.f;
    float acc3 = mk[4 * rsub + 3] ? bs[c] : 0.f;

#pragma unroll
    for (int k = 0; k < 16; k++) {
        float4 w  = Ws[c][k];
        float4 x0 = Xs[4 * rsub + 0][k];
        float4 x1 = Xs[4 * rsub + 1][k];
        float4 x2 = Xs[4 * rsub + 2][k];
        float4 x3 = Xs[4 * rsub + 3][k];
        acc0 += x0.x * w.x + x0.y * w.y + x0.z * w.z + x0.w * w.w;
        acc1 += x1.x * w.x + x1.y * w.y + x1.z * w.z + x1.w * w.w;
        acc2 += x2.x * w.x + x2.y * w.y + x2.z * w.z + x2.w * w.w;
        acc3 += x3.x * w.x + x3.y * w.y + x3.z * w.z + x3.w * w.w;
    }

    int rr = row0 + 4 * rsub;
    if (rr + 0 < N) out[(long long)(rr + 0) * 64 + c] = acc0;
    if (rr + 1 < N) out[(long long)(rr + 1) * 64 + c] = acc1;
    if (rr + 2 < N) out[(long long)(rr + 2) * 64 + c] = acc2;
    if (rr + 3 < N) out[(long long)(rr + 3) * 64 + c] = acc3;
}

// ---------------------------------------------------------------------------
extern "C" void kernel_launch(void* const* d_in, const int* in_sizes, int n_in,
                              void* d_out, int out_size) {
    const float* feat_user  = (const float*)d_in[0];
    const float* feat_item  = (const float*)d_in[1];
    const int*   src_clicks = (const int*)d_in[2];
    const int*   dst_clicks = (const int*)d_in[3];
    const int*   src_cb     = (const int*)d_in[4];
    const int*   dst_cb     = (const int*)d_in[5];
    const float* W_clicks   = (const float*)d_in[6];
    const float* b_clicks   = (const float*)d_in[7];
    const float* W_cb       = (const float*)d_in[8];
    const float* b_cb       = (const float*)d_in[9];

    int n_user = in_sizes[0] / 64;
    int n_item = in_sizes[1] / 64;
    int E1 = in_sizes[2];   // clicks edges      (user -> item)
    int E2 = in_sizes[4];   // clicked_by edges  (item -> user)
    int Emax = E1 > E2 ? E1 : E2;

    float* out_user = (float*)d_out;                         // [n_user, 64]
    float* out_item = out_user + (long long)n_user * 64;     // [n_item, 64]

    int n1 = n_item + 1, n2 = n_user + 1;
    int nb1 = (n1 + SCAN_B - 1) / SCAN_B;
    int nb2 = (n2 + SCAN_B - 1) / SCAN_B;
    int nmax = n_item > n_user ? n_item : n_user;

    // 1. zero counters
    zero_cnt<<<(nmax + 1 + 255) / 256, 256>>>(n_item, n_user);
    // 2. histogram (both relations)
    hist_kernel<<<(Emax + 255) / 256, 256>>>(dst_clicks, E1, dst_cb, E2);
    // 3-5. scan (both relations per launch)
    scan_block<<<nb1 + nb2, SCAN_B>>>(nb1, n1, n2);
    scan_bsums<<<2, 512>>>(nb1, nb2);
    scan_add<<<nb1 + nb2, SCAN_B>>>(nb1, n1, n2);
    // 6. reorder (both relations)
    reorder_kernel<<<(Emax + 255) / 256, 256>>>(src_clicks, dst_clicks, E1,
                                                src_cb, dst_cb, E2);
    // 7. segment-mean (both relations, one warp per dst)
    {
        long long threads = (long long)(n_item + n_user) * 32;
        int blocks = (int)((threads + 255) / 256);
        segmean_kernel<<<blocks, 256>>>((const float4*)feat_user,
                                        (const float4*)feat_item,
                                        n_item, n_user);
    }
    // 8. Linear -> d_out (both relations)
    {
        dim3 grid((nmax + 15) / 16, 2);
        linear_kernel<<<grid, 256>>>((const float4*)W_clicks, b_clicks,
                                     (const float4*)W_cb, b_cb,
                                     out_item, out_user, n_item, n_user);
    }
}